// round 7
// baseline (speedup 1.0000x reference)
#include <cuda_runtime.h>
#include <cstdint>

#define B_   256
#define T_   127
#define K_   128
#define H_   256
#define G4_  1024
#define BT_  (B_ * T_)       // 32512
#define CL_  8
#define MB_  16
#define HS_  32
#define NT_  512

__device__ float g_gx[(size_t)BT_ * G4_];    // [bt][row] x-gates + bias

// ----------------------------- helpers --------------------------------------
__device__ __forceinline__ unsigned smem_u32(const void* p) {
    return (unsigned)__cvta_generic_to_shared(p);
}
__device__ __forceinline__ unsigned mapa_rank(unsigned a, unsigned r) {
    unsigned ra; asm("mapa.shared::cluster.u32 %0, %1, %2;" : "=r"(ra) : "r"(a), "r"(r));
    return ra;
}
__device__ __forceinline__ void cluster_sync() {
    asm volatile("barrier.cluster.arrive.aligned;" ::: "memory");
    asm volatile("barrier.cluster.wait.aligned;" ::: "memory");
}
__device__ __forceinline__ void mbar_init(unsigned a, unsigned cnt) {
    asm volatile("mbarrier.init.shared.b64 [%0], %1;" :: "r"(a), "r"(cnt) : "memory");
}
__device__ __forceinline__ void mbar_expect_tx(unsigned a, unsigned bytes) {
    asm volatile("mbarrier.arrive.expect_tx.shared.b64 _, [%0], %1;"
                 :: "r"(a), "r"(bytes) : "memory");
}
__device__ __forceinline__ void mbar_arrive_remote(unsigned ra) {
    asm volatile("mbarrier.arrive.release.cluster.shared::cluster.b64 _, [%0];"
                 :: "r"(ra) : "memory");
}
__device__ __forceinline__ void st_async_f32(unsigned ra, float v, unsigned rmbar) {
    asm volatile("st.async.shared::cluster.mbarrier::complete_tx::bytes.b32 [%0], %1, [%2];"
                 :: "r"(ra), "r"(__float_as_uint(v)), "r"(rmbar) : "memory");
}
__device__ __forceinline__ void mbar_wait(unsigned a, unsigned parity) {
    unsigned done;
    asm volatile("{\n\t.reg .pred p;\n\t"
                 "mbarrier.try_wait.parity.acquire.cluster.shared::cta.b64 p, [%1], %2;\n\t"
                 "selp.b32 %0, 1, 0, p;\n\t}"
                 : "=r"(done) : "r"(a), "r"(parity) : "memory");
    if (!done) {
        asm volatile("{\n\t.reg .pred P1;\n\t"
                     "W_%=:\n\t"
                     "mbarrier.try_wait.parity.acquire.cluster.shared::cta.b64 P1, [%0], %1, 0x989680;\n\t"
                     "@P1 bra.uni D_%=;\n\t"
                     "bra.uni W_%=;\n\t"
                     "D_%=:\n\t}"
                     :: "r"(a), "r"(parity) : "memory");
    }
}
__device__ __forceinline__ float sigm(float x) { return 1.f / (1.f + __expf(-x)); }
__device__ __forceinline__ float ftanh(float x) { return 2.f / (1.f + __expf(-2.f * x)) - 1.f; }
__device__ __forceinline__ unsigned long long pack2(float v) {
    unsigned long long d; unsigned u = __float_as_uint(v);
    asm("mov.b64 %0, {%1, %1};" : "=l"(d) : "r"(u)); return d;
}
__device__ __forceinline__ void fma2(unsigned long long& a, unsigned long long w,
                                     unsigned long long x) {
    asm("fma.rn.f32x2 %0, %1, %2, %0;" : "+l"(a) : "l"(w), "l"(x));
}
__device__ __forceinline__ float2 unpack2(unsigned long long a) {
    unsigned lo, hi; asm("mov.b64 {%0, %1}, %2;" : "=r"(lo), "=r"(hi) : "l"(a));
    return make_float2(__uint_as_float(lo), __uint_as_float(hi));
}

// ---------------- Kernel A: softmax alpha + weight output (512 thr) ---------
__global__ void __launch_bounds__(512) k_alpha(const float* __restrict__ inp,
                                               const float* __restrict__ fc_w,
                                               float* __restrict__ out_w) {
    __shared__ float wx[128];
    __shared__ float part[4][128];
    __shared__ float redm[4], reds[4];
    const int tid = threadIdx.x, b = blockIdx.x;
    const int k = tid & 127, tq = tid >> 7;
    if (tid < 128) wx[tid] = (tid < T_) ? fc_w[2 * H_ + tid] : 0.f;
    __syncthreads();

    const float* ib = inp + (size_t)b * T_ * K_;
    float acc = 0.f;
    const int t0 = tq * 32, t1 = (t0 + 32 < T_) ? t0 + 32 : T_;
    for (int t = t0; t < t1; t++) acc += ib[t * K_ + k] * wx[t];
    part[tq][k] = acc;
    __syncthreads();

    float a = part[0][k] + part[1][k] + part[2][k] + part[3][k];
    float m = a;
#pragma unroll
    for (int o = 16; o; o >>= 1) m = fmaxf(m, __shfl_xor_sync(~0u, m, o));
    redm[(tid >> 5) & 3] = m;          // duplicate warps write identical values
    __syncthreads();
    m = fmaxf(fmaxf(redm[0], redm[1]), fmaxf(redm[2], redm[3]));
    float e = __expf(a - m), s = e;
#pragma unroll
    for (int o = 16; o; o >>= 1) s += __shfl_xor_sync(~0u, s, o);
    reds[(tid >> 5) & 3] = s;
    __syncthreads();
    s = reds[0] + reds[1] + reds[2] + reds[3];
    const float alpha = e / s;

    float* ob = out_w + (size_t)b * T_ * K_;
    for (int t = tq; t < T_; t += 4) ob[t * K_ + k] = alpha * ib[t * K_ + k];
}

// ---------------- Kernel X: g_gx = xw @ W_ih^T + bias -----------------------
#define XS_STR 68
#define WS_STR 132
#define GX_XS  (128 * XS_STR)
#define GX_WS  (128 * WS_STR)
#define GX_SMEMB ((GX_XS + GX_WS + 128) * 4)

__global__ void __launch_bounds__(NT_, 2) k_xgemm(const float* __restrict__ xw,
                                                  const float* __restrict__ W_ih,
                                                  const float* __restrict__ b_ih,
                                                  const float* __restrict__ b_hh) {
    extern __shared__ float s[];
    float* xs  = s;                    // [k][68]
    float* ws  = s + GX_XS;            // [k][132]
    float* bsm = ws + GX_WS;
    const int tid = threadIdx.x;
    const int mt = blockIdx.x >> 3, rt = blockIdx.x & 7;
    const int bt0 = mt * 64;

#pragma unroll
    for (int it = 0; it < 16; it++) {
        int idx = tid + NT_ * it;
        int k = idx & 127, b = idx >> 7;
        xs[k * XS_STR + b] = xw[(size_t)(bt0 + b) * K_ + k];
    }
#pragma unroll
    for (int it = 0; it < 32; it++) {
        int idx = tid + NT_ * it;
        int k = idx & 127, r = idx >> 7;
        ws[k * WS_STR + r] = W_ih[(rt * 128 + r) * K_ + k];
    }
    if (tid < 128) bsm[tid] = b_ih[rt * 128 + tid] + b_hh[rt * 128 + tid];
    __syncthreads();

    const int r = tid & 127, q = tid >> 7;
    const float* xq = xs + q * 16;
    unsigned long long A[8] = {0, 0, 0, 0, 0, 0, 0, 0};
#pragma unroll 4
    for (int k = 0; k < 128; k++) {
        unsigned long long w2 = pack2(ws[k * WS_STR + r]);
        const ulonglong2* xp = reinterpret_cast<const ulonglong2*>(xq + k * XS_STR);
        ulonglong2 x0 = xp[0], x1 = xp[1], x2 = xp[2], x3 = xp[3];
        fma2(A[0], w2, x0.x); fma2(A[1], w2, x0.y);
        fma2(A[2], w2, x1.x); fma2(A[3], w2, x1.y);
        fma2(A[4], w2, x2.x); fma2(A[5], w2, x2.y);
        fma2(A[6], w2, x3.x); fma2(A[7], w2, x3.y);
    }
    float bias = bsm[r];
    const size_t col = (size_t)rt * 128 + r;
#pragma unroll
    for (int j = 0; j < 8; j++) {
        float2 v = unpack2(A[j]);
        g_gx[(size_t)(bt0 + q * 16 + 2 * j)     * G4_ + col] = v.x + bias;
        g_gx[(size_t)(bt0 + q * 16 + 2 * j + 1) * G4_ + col] = v.y + bias;
    }
}

// ---------------- Kernel L: recurrence, mbarrier/st.async exchange ----------
#define HTSTR   5120                        // floats per h buffer (256*20)
#define GBSTR   4352                        // floats per gates buffer (2*128*17)
#define OFF_WH  0                           // [256 n][128 r]
#define OFF_HT  (OFF_WH + 256 * 128)        // [2][256 n][20 m]
#define OFF_GB  (OFF_HT + 2 * HTSTR)        // [2][2 nh][128 r][17]
#define OFF_BAR (OFF_GB + 2 * GBSTR)        // u64 barriers: full0 full1 empty0 empty1
#define L_SMEMB ((OFF_BAR + 16) * 4)        // ~206912 B

__global__ void __launch_bounds__(NT_, 1) __cluster_dims__(CL_, 1, 1)
k_lstm(const float* __restrict__ W_hh, float* __restrict__ out_h) {
    extern __shared__ float sm[];
    float* Wh = sm + OFF_WH;
    float* hT = sm + OFF_HT;
    float* gb = sm + OFF_GB;

    const int tid = threadIdx.x;
    unsigned rank; asm("mov.u32 %0, %%cluster_ctarank;" : "=r"(rank));
    const int b0 = (blockIdx.x / CL_) * MB_;
    const unsigned barB = smem_u32(sm + OFF_BAR);   // full[2] then empty[2]

    // stage W_hh slice transposed: Wh[n*128 + rl] = W_hh[grow(rl)*H + n]
#pragma unroll
    for (int it = 0; it < 64; it++) {
        int idx = tid + NT_ * it;
        int n = idx & 255, rl = idx >> 8;
        int grow = (rl >> 5) * H_ + (int)rank * HS_ + (rl & 31);
        Wh[n * 128 + rl] = W_hh[grow * H_ + n];
    }
#pragma unroll
    for (int it = 0; it < 20; it++) hT[tid + NT_ * it] = 0.f;   // both buffers

    if (tid == 0) {
        mbar_init(barB + 0, 1);   // full[0]
        mbar_init(barB + 8, 1);   // full[1]
        mbar_init(barB + 16, 8);  // empty[0]
        mbar_init(barB + 24, 8);  // empty[1]
    }

    // gemv roles
    const int r  = tid & 127;
    const int mh = (tid >> 7) & 1;
    const int nh = tid >> 8;
    const int grow_r = (r >> 5) * H_ + (int)rank * HS_ + (r & 31);
    const float* Wp = Wh + nh * (128 * 128) + r;
    float* gbp = gb + nh * (128 * 17) + r * 17 + mh * 8;

    // cell roles + remote addresses
    const int cjl = tid & 31, cm = tid >> 5;
    unsigned hdst[CL_], rfull[CL_], rempty[CL_];
    {
        unsigned la = smem_u32(&hT[((int)rank * HS_ + cjl) * 20 + cm]);
#pragma unroll
        for (unsigned pr = 0; pr < CL_; pr++) {
            hdst[pr]   = mapa_rank(la, pr);
            unsigned rb = mapa_rank(barB, pr);
            rfull[pr]  = rb;            // + (p^1)*8 at use
            rempty[pr] = rb + 16;       // + p*8 at use
        }
    }
    float c_reg = 0.f;
    float* outp = out_h + (size_t)(b0 + cm) * T_ * H_ + (int)rank * HS_ + cjl;

    __syncthreads();
    cluster_sync();                     // barriers + zeroed hT visible cluster-wide

    for (int t = 0; t < T_; t++) {
        const int p = t & 1;
        const unsigned pw = (unsigned)(((t - 1) >> 1) & 1);

        // prefetch x-gates (coalesced LDG, consumed after gemv)
        float gx0, gx1, gx2, gx3;
        {
            const int j0 = mh * 8 + nh * 4;
            const float* gp = g_gx + (size_t)((b0 + j0) * T_ + t) * G4_ + grow_r;
            const size_t st = (size_t)T_ * G4_;
            gx0 = gp[0]; gx1 = gp[st]; gx2 = gp[2 * st]; gx3 = gp[3 * st];
        }

        if (t > 0) mbar_wait(barB + p * 8, pw);     // full[p]: h arrived (acquire)

        // gemv over hT[p]: 128 n, 8 batches
        const float* Hp = hT + p * HTSTR + nh * (128 * 20) + mh * 8;
        unsigned long long A0 = 0, A1 = 0, A2 = 0, A3 = 0;
#pragma unroll 4
        for (int n = 0; n < 128; n++) {
            unsigned long long w2 = pack2(Wp[n * 128]);
            const ulonglong2* hp = reinterpret_cast<const ulonglong2*>(Hp + n * 20);
            ulonglong2 ha = hp[0], hb = hp[1];
            fma2(A0, w2, ha.x); fma2(A1, w2, ha.y);
            fma2(A2, w2, hb.x); fma2(A3, w2, hb.y);
        }
        float2 p0 = unpack2(A0), p1 = unpack2(A1), p2 = unpack2(A2), p3 = unpack2(A3);
        if (nh == 0) { p0.x += gx0; p0.y += gx1; p1.x += gx2; p1.y += gx3; }
        else         { p2.x += gx0; p2.y += gx1; p3.x += gx2; p3.y += gx3; }
        float* gq = gbp + p * GBSTR;
        gq[0] = p0.x; gq[1] = p0.y; gq[2] = p1.x; gq[3] = p1.y;
        gq[4] = p2.x; gq[5] = p2.y; gq[6] = p3.x; gq[7] = p3.y;
        __syncthreads();                 // hT[p] reads done; gb[p] visible

        if (t < T_ - 1 && tid == 0) {    // release our hT[p] to producers
#pragma unroll
            for (int pr = 0; pr < CL_; pr++) mbar_arrive_remote(rempty[pr] + p * 8);
        }

        // cell
        const float* g0 = gb + p * GBSTR;
        const float* g1 = g0 + 128 * 17;
        float gi = g0[cjl * 17 + cm]        + g1[cjl * 17 + cm];
        float gf = g0[(32 + cjl) * 17 + cm] + g1[(32 + cjl) * 17 + cm];
        float gg = g0[(64 + cjl) * 17 + cm] + g1[(64 + cjl) * 17 + cm];
        float go = g0[(96 + cjl) * 17 + cm] + g1[(96 + cjl) * 17 + cm];
        c_reg = sigm(gf) * c_reg + sigm(gi) * ftanh(gg);
        float hn = sigm(go) * ftanh(c_reg);

        *outp = hn; outp += H_;          // coalesced STG

        if (t < T_ - 1) {
            if (tid == 0) mbar_expect_tx(barB + (p ^ 1) * 8, 16384);
            if (t >= 1) mbar_wait(barB + 16 + (p ^ 1) * 8, pw);   // empty[p^1]
            const unsigned hoff = (unsigned)((p ^ 1) * HTSTR * 4);
            const unsigned boff = (unsigned)((p ^ 1) * 8);
#pragma unroll
            for (int pr = 0; pr < CL_; pr++)
                st_async_f32(hdst[pr] + hoff, hn, rfull[pr] + boff);
        }
    }
    cluster_sync();                      // drain async traffic before teardown
}

// ---------------- Launch -----------------------------------------------------
extern "C" void kernel_launch(void* const* d_in, const int* in_sizes, int n_in,
                              void* d_out, int out_size) {
    const float* input = (const float*)d_in[0];
    const float* W_ih  = (const float*)d_in[1];
    const float* W_hh  = (const float*)d_in[2];
    const float* b_ih  = (const float*)d_in[3];
    const float* b_hh  = (const float*)d_in[4];
    const float* fc_w  = (const float*)d_in[5];
    // d_in[6] = fc_b (cancels inside softmax)

    float* out   = (float*)d_out;
    float* out_w = out;                              // (B,T,K)
    float* out_h = out + (size_t)B_ * T_ * K_;       // (B,T,H)

    cudaFuncSetAttribute(k_xgemm, cudaFuncAttributeMaxDynamicSharedMemorySize, GX_SMEMB);
    cudaFuncSetAttribute(k_lstm,  cudaFuncAttributeMaxDynamicSharedMemorySize, L_SMEMB);

    k_alpha<<<B_, 512>>>(input, fc_w, out_w);
    k_xgemm<<<(BT_ / 64) * 8, NT_, GX_SMEMB>>>(out_w, W_ih, b_ih, b_hh);
    k_lstm<<<(B_ / MB_) * CL_, NT_, L_SMEMB>>>(W_hh, out_h);
}

// round 9
// speedup vs baseline: 2.1752x; 2.1752x over previous
#include <cuda_runtime.h>
#include <cuda_bf16.h>
#include <cstdint>

#define B_ 256
#define T_ 127
#define K_ 128
#define H_ 256
#define G4_ 1024
#define BT_ (B_ * T_)
#define CL_ 8

__device__ float g_gx[(size_t)BT_ * G4_];

__device__ __forceinline__ unsigned su32(const void* p) { return (unsigned)__cvta_generic_to_shared(p); }
__device__ __forceinline__ unsigned mapa_rank(unsigned a, unsigned r) {
    unsigned x; asm("mapa.shared::cluster.u32 %0, %1, %2;" : "=r"(x) : "r"(a), "r"(r)); return x;
}
__device__ __forceinline__ void csync() {
    asm volatile("barrier.cluster.arrive.aligned;" ::: "memory");
    asm volatile("barrier.cluster.wait.aligned;" ::: "memory");
}
__device__ __forceinline__ void mbar_init(unsigned a, unsigned c) {
    asm volatile("mbarrier.init.shared.b64 [%0], %1;" :: "r"(a), "r"(c) : "memory");
}
__device__ __forceinline__ void arr_remote(unsigned ra) {
    asm volatile("mbarrier.arrive.release.cluster.shared::cluster.b64 _, [%0];" :: "r"(ra) : "memory");
}
__device__ __forceinline__ void mwait(unsigned a, unsigned ph) {
    asm volatile("{.reg .pred P;\nLW%=:\n"
                 "mbarrier.try_wait.parity.acquire.cluster.shared::cta.b64 P, [%0], %1, 0x989680;\n"
                 "@P bra.uni LD%=;\nbra.uni LW%=;\nLD%=:\n}" :: "r"(a), "r"(ph) : "memory");
}
__device__ __forceinline__ void st_cl_v4(unsigned ra, uint4 v) {
    asm volatile("st.shared::cluster.v4.b32 [%0], {%1,%2,%3,%4};"
                 :: "r"(ra), "r"(v.x), "r"(v.y), "r"(v.z), "r"(v.w) : "memory");
}
__device__ __forceinline__ float sigm(float x) { return 1.f / (1.f + __expf(-x)); }
__device__ __forceinline__ float ftanh(float x) { return 2.f / (1.f + __expf(-2.f * x)) - 1.f; }
__device__ __forceinline__ unsigned long long pk2(float v) {
    unsigned long long d; unsigned u = __float_as_uint(v);
    asm("mov.b64 %0, {%1, %1};" : "=l"(d) : "r"(u)); return d;
}
__device__ __forceinline__ void fma2(unsigned long long& a, unsigned long long w, unsigned long long x) {
    asm("fma.rn.f32x2 %0, %1, %2, %0;" : "+l"(a) : "l"(w), "l"(x));
}
__device__ __forceinline__ float2 up2(unsigned long long a) {
    unsigned l, h; asm("mov.b64 {%0, %1}, %2;" : "=r"(l), "=r"(h) : "l"(a));
    return make_float2(__uint_as_float(l), __uint_as_float(h));
}

#define MMA(d, A, bb0, bb1) \
    asm volatile("mma.sync.aligned.m16n8k16.row.col.f32.bf16.bf16.f32 " \
                 "{%0,%1,%2,%3},{%4,%5,%6,%7},{%8,%9},{%0,%1,%2,%3};" \
                 : "+f"(d[0]), "+f"(d[1]), "+f"(d[2]), "+f"(d[3]) \
                 : "r"(A[0]), "r"(A[1]), "r"(A[2]), "r"(A[3]), "r"(bb0), "r"(bb1))
#define LDB(bb0, bb1, ad) \
    asm volatile("ldmatrix.sync.aligned.m8n8.x2.trans.shared.b16 {%0,%1}, [%2];" \
                 : "=r"(bb0), "=r"(bb1) : "r"(ad))
#define LDA(A, ad) \
    asm volatile("ldmatrix.sync.aligned.m8n8.x4.shared.b16 {%0,%1,%2,%3}, [%4];" \
                 : "=r"(A[0]), "=r"(A[1]), "=r"(A[2]), "=r"(A[3]) : "r"(ad))

// ---- k_alpha ---------------------------------------------------------------
__global__ void __launch_bounds__(512) k_alpha(const float* __restrict__ inp,
                                               const float* __restrict__ fc_w,
                                               float* __restrict__ ow) {
    __shared__ float wx[128], part[4][128], rm[4], rs[4];
    const int tid = threadIdx.x, b = blockIdx.x, k = tid & 127, tq = tid >> 7;
    if (tid < 128) wx[tid] = (tid < T_) ? fc_w[2 * H_ + tid] : 0.f;
    __syncthreads();
    const float* ib = inp + (size_t)b * T_ * K_;
    float acc = 0.f;
    const int t1 = (tq * 32 + 32 < T_) ? tq * 32 + 32 : T_;
    for (int t = tq * 32; t < t1; t++) acc += ib[t * K_ + k] * wx[t];
    part[tq][k] = acc;
    __syncthreads();
    float a = part[0][k] + part[1][k] + part[2][k] + part[3][k];
    float m = a;
#pragma unroll
    for (int o = 16; o; o >>= 1) m = fmaxf(m, __shfl_xor_sync(~0u, m, o));
    rm[(tid >> 5) & 3] = m; __syncthreads();
    m = fmaxf(fmaxf(rm[0], rm[1]), fmaxf(rm[2], rm[3]));
    float e = __expf(a - m), s = e;
#pragma unroll
    for (int o = 16; o; o >>= 1) s += __shfl_xor_sync(~0u, s, o);
    rs[(tid >> 5) & 3] = s; __syncthreads();
    const float al = e / (rs[0] + rs[1] + rs[2] + rs[3]);
    float* ob = ow + (size_t)b * T_ * K_;
    for (int t = tq; t < T_; t += 4) ob[t * K_ + k] = al * ib[t * K_ + k];
}

// ---- k_xgemm: g_gx = xw @ W_ih^T + bias (proven R4 version) -----------------
#define GXB ((128 * 68 + 128 * 132 + 128) * 4)
__global__ void __launch_bounds__(512, 2) k_xgemm(const float* __restrict__ xw,
                                                  const float* __restrict__ Wih,
                                                  const float* __restrict__ bi,
                                                  const float* __restrict__ bh) {
    extern __shared__ float s[];
    float* xs = s; float* ws = s + 128 * 68; float* bs = ws + 128 * 132;
    const int tid = threadIdx.x, mt = blockIdx.x >> 3, rt = blockIdx.x & 7, bt0 = mt * 64;
#pragma unroll
    for (int i = 0; i < 16; i++) {
        int x = tid + 512 * i, k = x & 127, b = x >> 7;
        xs[k * 68 + b] = xw[(size_t)(bt0 + b) * K_ + k];
    }
#pragma unroll
    for (int i = 0; i < 32; i++) {
        int x = tid + 512 * i, k = x & 127, r = x >> 7;
        ws[k * 132 + r] = Wih[(rt * 128 + r) * K_ + k];
    }
    if (tid < 128) bs[tid] = bi[rt * 128 + tid] + bh[rt * 128 + tid];
    __syncthreads();
    const int r = tid & 127, q = tid >> 7;
    const float* xq = xs + q * 16;
    unsigned long long A[8] = {0,0,0,0,0,0,0,0};
#pragma unroll 4
    for (int k = 0; k < 128; k++) {
        unsigned long long w2 = pk2(ws[k * 132 + r]);
        const ulonglong2* xp = (const ulonglong2*)(xq + k * 68);
        ulonglong2 a0 = xp[0], a1 = xp[1], a2 = xp[2], a3 = xp[3];
        fma2(A[0], w2, a0.x); fma2(A[1], w2, a0.y); fma2(A[2], w2, a1.x); fma2(A[3], w2, a1.y);
        fma2(A[4], w2, a2.x); fma2(A[5], w2, a2.y); fma2(A[6], w2, a3.x); fma2(A[7], w2, a3.y);
    }
    float bia = bs[r]; const size_t col = (size_t)rt * 128 + r;
#pragma unroll
    for (int j = 0; j < 8; j++) {
        float2 v = up2(A[j]);
        g_gx[(size_t)(bt0 + q * 16 + 2 * j) * G4_ + col] = v.x + bia;
        g_gx[(size_t)(bt0 + q * 16 + 2 * j + 1) * G4_ + col] = v.y + bia;
    }
}

// ---- k_lstm: mma.sync recurrence -------------------------------------------
// smem: barriers@0 (full0,full1,empty0,empty1); hT@1024 [2][2][256][16]bf16 (32KB);
// gt@33792 [128][18]f (9216B); hs@43008 [2][32][16]bf16 (2KB); Wst@45056 (64KB)
#define LSMB 110592
__global__ void __launch_bounds__(256, 1) __cluster_dims__(CL_, 1, 1)
k_lstm(const float* __restrict__ W_hh, float* __restrict__ out_h) {
    extern __shared__ __align__(1024) char smc[];
    float* smf = (float*)smc;
    const int tid = threadIdx.x, wid = tid >> 5, lane = tid & 31;
    unsigned rank; asm("mov.u32 %0, %%cluster_ctarank;" : "=r"(rank));
    const int b0 = (blockIdx.x / CL_) * 16;
    const unsigned sb = su32(smc);

    if (tid == 0) {
        mbar_init(sb + 0, 1024); mbar_init(sb + 8, 1024);   // full[0], full[1]
        mbar_init(sb + 16, 8);   mbar_init(sb + 24, 8);     // empty[0], empty[1]
    }
    for (int i = tid; i < 8192; i += 256) smf[256 + i] = 0.f;   // zero hT

    // ---- preload W A-fragments (hi then lo) ----
    __nv_bfloat16* Wst = (__nv_bfloat16*)(smc + 45056);
    unsigned ahi[16][4], alo[16][4];
    const unsigned abase = su32(Wst) + (unsigned)((wid * 16 + (lane & 15)) * 512 + (lane >> 4) * 16);
    for (int i = tid; i < 32768; i += 256) {
        int r = i >> 8, k = i & 255;
        int grow = (r >> 5) * H_ + (int)rank * 32 + (r & 31);
        Wst[r * 256 + k] = __float2bfloat16(W_hh[grow * H_ + k]);
    }
    __syncthreads();
#pragma unroll
    for (int kc = 0; kc < 16; kc++) LDA(ahi[kc], abase + kc * 32);
    __syncthreads();
    for (int i = tid; i < 32768; i += 256) {
        int r = i >> 8, k = i & 255;
        int grow = (r >> 5) * H_ + (int)rank * 32 + (r & 31);
        float w = W_hh[grow * H_ + k];
        Wst[r * 256 + k] = __float2bfloat16(w - __bfloat162float(__float2bfloat16(w)));
    }
    __syncthreads();
#pragma unroll
    for (int kc = 0; kc < 16; kc++) LDA(alo[kc], abase + kc * 32);
    __syncthreads();

    unsigned rbase[CL_];
#pragma unroll
    for (int pr = 0; pr < CL_; pr++) rbase[pr] = mapa_rank(sb, pr);

    const unsigned hT0 = sb + 1024;
    const unsigned brow = (unsigned)((lane & 15) * 32);

    // cell roles: (jl, batches m0 and m0+8)
    const int jl = tid & 31, m0 = tid >> 5;
    float c0 = 0.f, c1 = 0.f;
    float* gt = (float*)(smc + 33792);
    __nv_bfloat16* hs = (__nv_bfloat16*)(smc + 43008);
    float* o0 = out_h + (size_t)(b0 + m0) * T_ * H_ + (int)rank * 32 + jl;
    float* o1 = out_h + (size_t)(b0 + m0 + 8) * T_ * H_ + (int)rank * 32 + jl;
    const float* gxb = g_gx + (size_t)b0 * T_ * G4_ + (int)rank * 32 + jl;

    // writer roles: chunk wc -> (jl, batch-half, hi/lo); ranks rg..rg+3
    const int wc = tid & 127;
    const int wjl = wc >> 2, whalf = (wc >> 1) & 1, whl = wc & 1;
    const int rg = (tid >> 7) * 4;
    const uint4* wsrc = (const uint4*)(smc + 43008 + whl * 1024 + wjl * 32 + whalf * 16);
    const unsigned wdst = (unsigned)(1024 + whl * 8192 + ((int)rank * 32 + wjl) * 32 + whalf * 16);

    csync();

    for (int t = 0; t < T_; t++) {
        const int p = t & 1;
        const unsigned pw = (unsigned)(((t - 1) >> 1) & 1);

        // prefetch gx (8 coalesced LDG, used in cell)
        const float* gp = gxb + (size_t)t * G4_;
        float gx[8];
#pragma unroll
        for (int q = 0; q < 4; q++) {
            gx[q]     = gp[(size_t)m0 * T_ * G4_ + q * 256];
            gx[4 + q] = gp[(size_t)(m0 + 8) * T_ * G4_ + q * 256];
        }

        float d0[4] = {0.f, 0.f, 0.f, 0.f}, d1[4] = {0.f, 0.f, 0.f, 0.f};
        if (t > 0) {
            mwait(sb + p * 8, pw);                       // full[p]: h arrived
            const unsigned bb = hT0 + (unsigned)p * 16384 + brow;
#pragma unroll
            for (int kc = 0; kc < 16; kc++) {
                unsigned bh0, bh1, bl0, bl1;
                LDB(bh0, bh1, bb + kc * 512);
                LDB(bl0, bl1, bb + 8192 + kc * 512);
                MMA(d0, ahi[kc], bh0, bh1);
                MMA(d0, alo[kc], bh0, bh1);
                MMA(d0, ahi[kc], bl0, bl1);
                LDB(bh0, bh1, bb + kc * 512 + 16);
                LDB(bl0, bl1, bb + 8192 + kc * 512 + 16);
                MMA(d1, ahi[kc], bh0, bh1);
                MMA(d1, alo[kc], bh0, bh1);
                MMA(d1, ahi[kc], bl0, bl1);
            }
        }
        {   // D -> gt
            int g = lane >> 2, tt = (lane & 3) * 2;
            float* r0 = gt + (wid * 16 + g) * 18;
            float* r1 = r0 + 8 * 18;
            *(float2*)(r0 + tt) = make_float2(d0[0], d0[1]);
            *(float2*)(r1 + tt) = make_float2(d0[2], d0[3]);
            *(float2*)(r0 + 8 + tt) = make_float2(d1[0], d1[1]);
            *(float2*)(r1 + 8 + tt) = make_float2(d1[2], d1[3]);
        }
        __syncthreads();                                 // hT[p] reads + gt done
        if (tid < 8) arr_remote(rbase[tid] + 16 + p * 8);   // release empty[p]

        // cell (gates = gt + gx)
        float gi = gt[jl * 18 + m0] + gx[0];
        float gf = gt[(32 + jl) * 18 + m0] + gx[1];
        float gg = gt[(64 + jl) * 18 + m0] + gx[2];
        float go = gt[(96 + jl) * 18 + m0] + gx[3];
        c0 = sigm(gf) * c0 + sigm(gi) * ftanh(gg);
        float h0 = sigm(go) * ftanh(c0);
        gi = gt[jl * 18 + m0 + 8] + gx[4];
        gf = gt[(32 + jl) * 18 + m0 + 8] + gx[5];
        gg = gt[(64 + jl) * 18 + m0 + 8] + gx[6];
        go = gt[(96 + jl) * 18 + m0 + 8] + gx[7];
        c1 = sigm(gf) * c1 + sigm(gi) * ftanh(gg);
        float h1 = sigm(go) * ftanh(c1);

        o0[(size_t)t * H_] = h0;                         // coalesced STG
        o1[(size_t)t * H_] = h1;

        if (t < T_ - 1) {
            __nv_bfloat16 hh0 = __float2bfloat16(h0), hh1 = __float2bfloat16(h1);
            hs[jl * 16 + m0] = hh0;
            hs[jl * 16 + m0 + 8] = hh1;
            hs[512 + jl * 16 + m0] = __float2bfloat16(h0 - __bfloat162float(hh0));
            hs[512 + jl * 16 + m0 + 8] = __float2bfloat16(h1 - __bfloat162float(hh1));
            __syncthreads();                             // hs complete
            if (t > 0) mwait(sb + 16 + (p ^ 1) * 8, pw); // empty[p^1]
            uint4 v = *wsrc;
            unsigned drel = wdst + (unsigned)((p ^ 1) * 16384);
#pragma unroll
            for (int i = 0; i < 4; i++) {
                st_cl_v4(rbase[rg + i] + drel, v);
                arr_remote(rbase[rg + i] + (p ^ 1) * 8); // full[p^1] (release)
            }
        }
    }
    csync();
}

// ---- launch -----------------------------------------------------------------
extern "C" void kernel_launch(void* const* d_in, const int* in_sizes, int n_in,
                              void* d_out, int out_size) {
    const float* input = (const float*)d_in[0];
    const float* W_ih  = (const float*)d_in[1];
    const float* W_hh  = (const float*)d_in[2];
    const float* b_ih  = (const float*)d_in[3];
    const float* b_hh  = (const float*)d_in[4];
    const float* fc_w  = (const float*)d_in[5];
    float* out   = (float*)d_out;
    float* out_w = out;
    float* out_h = out + (size_t)B_ * T_ * K_;

    cudaFuncSetAttribute(k_xgemm, cudaFuncAttributeMaxDynamicSharedMemorySize, GXB);
    cudaFuncSetAttribute(k_lstm,  cudaFuncAttributeMaxDynamicSharedMemorySize, LSMB);

    k_alpha<<<B_, 512>>>(input, fc_w, out_w);
    k_xgemm<<<(BT_ / 64) * 8, 512, GXB>>>(out_w, W_ih, b_ih, b_hh);
    k_lstm<<<(B_ / 16) * CL_, 256, LSMB>>>(W_hh, out_h);
}

// round 10
// speedup vs baseline: 2.7145x; 1.2479x over previous
#include <cuda_runtime.h>
#include <cuda_bf16.h>
#include <cstdint>

#define B_ 256
#define T_ 127
#define K_ 128
#define H_ 256
#define G4_ 1024
#define BT_ (B_ * T_)
#define CL_ 8

__device__ float g_gx[(size_t)BT_ * G4_];

__device__ __forceinline__ unsigned su32(const void* p) { return (unsigned)__cvta_generic_to_shared(p); }
__device__ __forceinline__ unsigned mapa_rank(unsigned a, unsigned r) {
    unsigned x; asm("mapa.shared::cluster.u32 %0, %1, %2;" : "=r"(x) : "r"(a), "r"(r)); return x;
}
__device__ __forceinline__ void csync() {
    asm volatile("barrier.cluster.arrive.aligned;" ::: "memory");
    asm volatile("barrier.cluster.wait.aligned;" ::: "memory");
}
__device__ __forceinline__ void mbar_init(unsigned a, unsigned c) {
    asm volatile("mbarrier.init.shared.b64 [%0], %1;" :: "r"(a), "r"(c) : "memory");
}
__device__ __forceinline__ void arr_remote(unsigned ra) {
    asm volatile("mbarrier.arrive.release.cluster.shared::cluster.b64 _, [%0];" :: "r"(ra) : "memory");
}
__device__ __forceinline__ void mwait(unsigned a, unsigned ph) {
    asm volatile("{.reg .pred P;\nLW%=:\n"
                 "mbarrier.try_wait.parity.acquire.cluster.shared::cta.b64 P, [%0], %1, 0x989680;\n"
                 "@P bra.uni LD%=;\nbra.uni LW%=;\nLD%=:\n}" :: "r"(a), "r"(ph) : "memory");
}
__device__ __forceinline__ void st_cl_v4(unsigned ra, uint4 v) {
    asm volatile("st.shared::cluster.v4.b32 [%0], {%1,%2,%3,%4};"
                 :: "r"(ra), "r"(v.x), "r"(v.y), "r"(v.z), "r"(v.w) : "memory");
}
__device__ __forceinline__ float sigm(float x) { return 1.f / (1.f + __expf(-x)); }
__device__ __forceinline__ float ftanh(float x) { return 2.f / (1.f + __expf(-2.f * x)) - 1.f; }
__device__ __forceinline__ unsigned long long pk2(float v) {
    unsigned long long d; unsigned u = __float_as_uint(v);
    asm("mov.b64 %0, {%1, %1};" : "=l"(d) : "r"(u)); return d;
}
__device__ __forceinline__ void fma2(unsigned long long& a, unsigned long long w, unsigned long long x) {
    asm("fma.rn.f32x2 %0, %1, %2, %0;" : "+l"(a) : "l"(w), "l"(x));
}
__device__ __forceinline__ float2 up2(unsigned long long a) {
    unsigned l, h; asm("mov.b64 {%0, %1}, %2;" : "=r"(l), "=r"(h) : "l"(a));
    return make_float2(__uint_as_float(l), __uint_as_float(h));
}

#define MMA(d, A, bb0, bb1) \
    asm volatile("mma.sync.aligned.m16n8k16.row.col.f32.bf16.bf16.f32 " \
                 "{%0,%1,%2,%3},{%4,%5,%6,%7},{%8,%9},{%0,%1,%2,%3};" \
                 : "+f"(d[0]), "+f"(d[1]), "+f"(d[2]), "+f"(d[3]) \
                 : "r"(A[0]), "r"(A[1]), "r"(A[2]), "r"(A[3]), "r"(bb0), "r"(bb1))
#define LDB(bb0, bb1, ad) \
    asm volatile("ldmatrix.sync.aligned.m8n8.x2.trans.shared.b16 {%0,%1}, [%2];" \
                 : "=r"(bb0), "=r"(bb1) : "r"(ad))
#define LDA(A, ad) \
    asm volatile("ldmatrix.sync.aligned.m8n8.x4.shared.b16 {%0,%1,%2,%3}, [%4];" \
                 : "=r"(A[0]), "=r"(A[1]), "=r"(A[2]), "=r"(A[3]) : "r"(ad))

// ---- k_alpha ---------------------------------------------------------------
__global__ void __launch_bounds__(512) k_alpha(const float* __restrict__ inp,
                                               const float* __restrict__ fc_w,
                                               float* __restrict__ ow) {
    __shared__ float wx[128], part[4][128], rm[4], rs[4];
    const int tid = threadIdx.x, b = blockIdx.x, k = tid & 127, tq = tid >> 7;
    if (tid < 128) wx[tid] = (tid < T_) ? fc_w[2 * H_ + tid] : 0.f;
    __syncthreads();
    const float* ib = inp + (size_t)b * T_ * K_;
    float acc = 0.f;
    const int t1 = (tq * 32 + 32 < T_) ? tq * 32 + 32 : T_;
    for (int t = tq * 32; t < t1; t++) acc += ib[t * K_ + k] * wx[t];
    part[tq][k] = acc;
    __syncthreads();
    float a = part[0][k] + part[1][k] + part[2][k] + part[3][k];
    float m = a;
#pragma unroll
    for (int o = 16; o; o >>= 1) m = fmaxf(m, __shfl_xor_sync(~0u, m, o));
    rm[(tid >> 5) & 3] = m; __syncthreads();
    m = fmaxf(fmaxf(rm[0], rm[1]), fmaxf(rm[2], rm[3]));
    float e = __expf(a - m), s = e;
#pragma unroll
    for (int o = 16; o; o >>= 1) s += __shfl_xor_sync(~0u, s, o);
    rs[(tid >> 5) & 3] = s; __syncthreads();
    const float al = e / (rs[0] + rs[1] + rs[2] + rs[3]);
    float* ob = ow + (size_t)b * T_ * K_;
    for (int t = tq; t < T_; t += 4) ob[t * K_ + k] = al * ib[t * K_ + k];
}

// ---- k_xgemm: g_gx = xw @ W_ih^T + bias -------------------------------------
#define GXB ((128 * 68 + 128 * 132 + 128) * 4)
__global__ void __launch_bounds__(512, 2) k_xgemm(const float* __restrict__ xw,
                                                  const float* __restrict__ Wih,
                                                  const float* __restrict__ bi,
                                                  const float* __restrict__ bh) {
    extern __shared__ float s[];
    float* xs = s; float* ws = s + 128 * 68; float* bs = ws + 128 * 132;
    const int tid = threadIdx.x, mt = blockIdx.x >> 3, rt = blockIdx.x & 7, bt0 = mt * 64;
#pragma unroll
    for (int i = 0; i < 16; i++) {
        int x = tid + 512 * i, k = x & 127, b = x >> 7;
        xs[k * 68 + b] = xw[(size_t)(bt0 + b) * K_ + k];
    }
#pragma unroll
    for (int i = 0; i < 32; i++) {
        int x = tid + 512 * i, k = x & 127, r = x >> 7;
        ws[k * 132 + r] = Wih[(rt * 128 + r) * K_ + k];
    }
    if (tid < 128) bs[tid] = bi[rt * 128 + tid] + bh[rt * 128 + tid];
    __syncthreads();
    const int r = tid & 127, q = tid >> 7;
    const float* xq = xs + q * 16;
    unsigned long long A[8] = {0,0,0,0,0,0,0,0};
#pragma unroll 4
    for (int k = 0; k < 128; k++) {
        unsigned long long w2 = pk2(ws[k * 132 + r]);
        const ulonglong2* xp = (const ulonglong2*)(xq + k * 68);
        ulonglong2 a0 = xp[0], a1 = xp[1], a2 = xp[2], a3 = xp[3];
        fma2(A[0], w2, a0.x); fma2(A[1], w2, a0.y); fma2(A[2], w2, a1.x); fma2(A[3], w2, a1.y);
        fma2(A[4], w2, a2.x); fma2(A[5], w2, a2.y); fma2(A[6], w2, a3.x); fma2(A[7], w2, a3.y);
    }
    float bia = bs[r]; const size_t col = (size_t)rt * 128 + r;
#pragma unroll
    for (int j = 0; j < 8; j++) {
        float2 v = up2(A[j]);
        g_gx[(size_t)(bt0 + q * 16 + 2 * j) * G4_ + col] = v.x + bia;
        g_gx[(size_t)(bt0 + q * 16 + 2 * j + 1) * G4_ + col] = v.y + bia;
    }
}

// ---- k_lstm: mma.sync recurrence, count-8 barriers, split chains ------------
#define LSMB 110592
__global__ void __launch_bounds__(256, 1) __cluster_dims__(CL_, 1, 1)
k_lstm(const float* __restrict__ W_hh, float* __restrict__ out_h) {
    extern __shared__ __align__(1024) char smc[];
    float* smf = (float*)smc;
    const int tid = threadIdx.x, wid = tid >> 5, lane = tid & 31;
    unsigned rank; asm("mov.u32 %0, %%cluster_ctarank;" : "=r"(rank));
    const int b0 = (blockIdx.x / CL_) * 16;
    const unsigned sb = su32(smc);

    if (tid == 0) {
        mbar_init(sb + 0, 8);  mbar_init(sb + 8, 8);    // full[0], full[1]
        mbar_init(sb + 16, 8); mbar_init(sb + 24, 8);   // empty[0], empty[1]
    }
    for (int i = tid; i < 8192; i += 256) smf[256 + i] = 0.f;   // zero hT

    // ---- preload W A-fragments (hi then lo) ----
    __nv_bfloat16* Wst = (__nv_bfloat16*)(smc + 45056);
    unsigned ahi[16][4], alo[16][4];
    const unsigned abase = su32(Wst) + (unsigned)((wid * 16 + (lane & 15)) * 512 + (lane >> 4) * 16);
    for (int i = tid; i < 32768; i += 256) {
        int r = i >> 8, k = i & 255;
        int grow = (r >> 5) * H_ + (int)rank * 32 + (r & 31);
        Wst[r * 256 + k] = __float2bfloat16(W_hh[grow * H_ + k]);
    }
    __syncthreads();
#pragma unroll
    for (int kc = 0; kc < 16; kc++) LDA(ahi[kc], abase + kc * 32);
    __syncthreads();
    for (int i = tid; i < 32768; i += 256) {
        int r = i >> 8, k = i & 255;
        int grow = (r >> 5) * H_ + (int)rank * 32 + (r & 31);
        float w = W_hh[grow * H_ + k];
        Wst[r * 256 + k] = __float2bfloat16(w - __bfloat162float(__float2bfloat16(w)));
    }
    __syncthreads();
#pragma unroll
    for (int kc = 0; kc < 16; kc++) LDA(alo[kc], abase + kc * 32);
    __syncthreads();

    unsigned rbase[CL_];
#pragma unroll
    for (int pr = 0; pr < CL_; pr++) rbase[pr] = mapa_rank(sb, pr);

    const unsigned hT0 = sb + 1024;
    const unsigned brow = (unsigned)((lane & 15) * 32);

    const int jl = tid & 31, m0 = tid >> 5;
    float c0 = 0.f, c1 = 0.f;
    float* gt = (float*)(smc + 33792);
    __nv_bfloat16* hs = (__nv_bfloat16*)(smc + 43008);
    float* o0 = out_h + (size_t)(b0 + m0) * T_ * H_ + (int)rank * 32 + jl;
    float* o1 = out_h + (size_t)(b0 + m0 + 8) * T_ * H_ + (int)rank * 32 + jl;
    const float* gxb = g_gx + (size_t)b0 * T_ * G4_ + (int)rank * 32 + jl;

    const int wc = tid & 127;
    const int wjl = wc >> 2, whalf = (wc >> 1) & 1, whl = wc & 1;
    const int rg = (tid >> 7) * 4;
    const uint4* wsrc = (const uint4*)(smc + 43008 + whl * 1024 + wjl * 32 + whalf * 16);
    const unsigned wdst = (unsigned)(1024 + whl * 8192 + ((int)rank * 32 + wjl) * 32 + whalf * 16);

    csync();

    for (int t = 0; t < T_; t++) {
        const int p = t & 1;
        const unsigned pw = (unsigned)(((t - 1) >> 1) & 1);

        const float* gp = gxb + (size_t)t * G4_;
        float gx[8];
#pragma unroll
        for (int q = 0; q < 4; q++) {
            gx[q]     = gp[(size_t)m0 * T_ * G4_ + q * 256];
            gx[4 + q] = gp[(size_t)(m0 + 8) * T_ * G4_ + q * 256];
        }

        float d0[4] = {0.f, 0.f, 0.f, 0.f}, d1[4] = {0.f, 0.f, 0.f, 0.f};
        if (t > 0) {
            if (wid == 0) mwait(sb + p * 8, pw);         // full[p]
            __syncthreads();
            const unsigned bb = hT0 + (unsigned)p * 16384 + brow;
            float a0[4] = {0,0,0,0}, b0a[4] = {0,0,0,0}, cc0[4] = {0,0,0,0};
            float a1[4] = {0,0,0,0}, b1a[4] = {0,0,0,0}, cc1[4] = {0,0,0,0};
#pragma unroll
            for (int kc = 0; kc < 16; kc++) {
                unsigned bh0, bh1, bl0, bl1, ch0, ch1, cl0, cl1;
                LDB(bh0, bh1, bb + kc * 512);
                LDB(bl0, bl1, bb + 8192 + kc * 512);
                LDB(ch0, ch1, bb + kc * 512 + 16);
                LDB(cl0, cl1, bb + 8192 + kc * 512 + 16);
                MMA(a0, ahi[kc], bh0, bh1);
                MMA(b0a, alo[kc], bh0, bh1);
                MMA(cc0, ahi[kc], bl0, bl1);
                MMA(a1, ahi[kc], ch0, ch1);
                MMA(b1a, alo[kc], ch0, ch1);
                MMA(cc1, ahi[kc], cl0, cl1);
            }
#pragma unroll
            for (int i = 0; i < 4; i++) {
                d0[i] = a0[i] + b0a[i] + cc0[i];
                d1[i] = a1[i] + b1a[i] + cc1[i];
            }
        }
        {   // D -> gt
            int g = lane >> 2, tt = (lane & 3) * 2;
            float* r0 = gt + (wid * 16 + g) * 18;
            float* r1 = r0 + 8 * 18;
            *(float2*)(r0 + tt) = make_float2(d0[0], d0[1]);
            *(float2*)(r1 + tt) = make_float2(d0[2], d0[3]);
            *(float2*)(r0 + 8 + tt) = make_float2(d1[0], d1[1]);
            *(float2*)(r1 + 8 + tt) = make_float2(d1[2], d1[3]);
        }
        __syncthreads();                                 // hT[p] reads + gt done
        if (tid < 8) arr_remote(rbase[tid] + 16 + p * 8);   // release empty[p]

        float gi = gt[jl * 18 + m0] + gx[0];
        float gf = gt[(32 + jl) * 18 + m0] + gx[1];
        float gg = gt[(64 + jl) * 18 + m0] + gx[2];
        float go = gt[(96 + jl) * 18 + m0] + gx[3];
        c0 = sigm(gf) * c0 + sigm(gi) * ftanh(gg);
        float h0 = sigm(go) * ftanh(c0);
        gi = gt[jl * 18 + m0 + 8] + gx[4];
        gf = gt[(32 + jl) * 18 + m0 + 8] + gx[5];
        gg = gt[(64 + jl) * 18 + m0 + 8] + gx[6];
        go = gt[(96 + jl) * 18 + m0 + 8] + gx[7];
        c1 = sigm(gf) * c1 + sigm(gi) * ftanh(gg);
        float h1 = sigm(go) * ftanh(c1);

        o0[(size_t)t * H_] = h0;
        o1[(size_t)t * H_] = h1;

        if (t < T_ - 1) {
            __nv_bfloat16 hh0 = __float2bfloat16(h0), hh1 = __float2bfloat16(h1);
            hs[jl * 16 + m0] = hh0;
            hs[jl * 16 + m0 + 8] = hh1;
            hs[512 + jl * 16 + m0] = __float2bfloat16(h0 - __bfloat162float(hh0));
            hs[512 + jl * 16 + m0 + 8] = __float2bfloat16(h1 - __bfloat162float(hh1));
            if (wid == 0 && t > 0) mwait(sb + 16 + (p ^ 1) * 8, pw);   // empty[p^1]
            __syncthreads();                             // hs ready + empty acquired
            uint4 v = *wsrc;
            unsigned drel = wdst + (unsigned)((p ^ 1) * 16384);
#pragma unroll
            for (int i = 0; i < 4; i++) st_cl_v4(rbase[rg + i] + drel, v);
            __syncthreads();                             // all remote stores issued
            if (tid < 8) arr_remote(rbase[tid] + (p ^ 1) * 8);   // full[p^1] release
        }
    }
    csync();
}

// ---- launch -----------------------------------------------------------------
extern "C" void kernel_launch(void* const* d_in, const int* in_sizes, int n_in,
                              void* d_out, int out_size) {
    const float* input = (const float*)d_in[0];
    const float* W_ih  = (const float*)d_in[1];
    const float* W_hh  = (const float*)d_in[2];
    const float* b_ih  = (const float*)d_in[3];
    const float* b_hh  = (const float*)d_in[4];
    const float* fc_w  = (const float*)d_in[5];
    float* out   = (float*)d_out;
    float* out_w = out;
    float* out_h = out + (size_t)B_ * T_ * K_;

    cudaFuncSetAttribute(k_xgemm, cudaFuncAttributeMaxDynamicSharedMemorySize, GXB);
    cudaFuncSetAttribute(k_lstm,  cudaFuncAttributeMaxDynamicSharedMemorySize, LSMB);

    k_alpha<<<B_, 512>>>(input, fc_w, out_w);
    k_xgemm<<<(BT_ / 64) * 8, 512, GXB>>>(out_w, W_ih, b_ih, b_hh);
    k_lstm<<<(B_ / 16) * CL_, 256, LSMB>>>(W_hh, out_h);
}

// round 12
// speedup vs baseline: 3.0374x; 1.1190x over previous
#include <cuda_runtime.h>
#include <cuda_bf16.h>
#include <cstdint>

#define B_ 256
#define T_ 127
#define K_ 128
#define H_ 256
#define G4_ 1024
#define BT_ (B_ * T_)
#define CL_ 8

__device__ float g_gx[(size_t)BT_ * G4_];

__device__ __forceinline__ unsigned su32(const void* p) { return (unsigned)__cvta_generic_to_shared(p); }
__device__ __forceinline__ unsigned mapa_rank(unsigned a, unsigned r) {
    unsigned x; asm("mapa.shared::cluster.u32 %0, %1, %2;" : "=r"(x) : "r"(a), "r"(r)); return x;
}
__device__ __forceinline__ void csync() {
    asm volatile("barrier.cluster.arrive.aligned;" ::: "memory");
    asm volatile("barrier.cluster.wait.aligned;" ::: "memory");
}
__device__ __forceinline__ void mbar_init(unsigned a, unsigned c) {
    asm volatile("mbarrier.init.shared.b64 [%0], %1;" :: "r"(a), "r"(c) : "memory");
}
__device__ __forceinline__ void arr_remote(unsigned ra) {
    asm volatile("mbarrier.arrive.release.cluster.shared::cluster.b64 _, [%0];" :: "r"(ra) : "memory");
}
__device__ __forceinline__ void mwait(unsigned a, unsigned ph) {
    asm volatile("{.reg .pred P;\nLW%=:\n"
                 "mbarrier.try_wait.parity.acquire.cluster.shared::cta.b64 P, [%0], %1, 0x989680;\n"
                 "@P bra.uni LD%=;\nbra.uni LW%=;\nLD%=:\n}" :: "r"(a), "r"(ph) : "memory");
}
__device__ __forceinline__ void st_cl_v4(unsigned ra, uint4 v) {
    asm volatile("st.shared::cluster.v4.b32 [%0], {%1,%2,%3,%4};"
                 :: "r"(ra), "r"(v.x), "r"(v.y), "r"(v.z), "r"(v.w) : "memory");
}
__device__ __forceinline__ float sigm(float x) { return 1.f / (1.f + __expf(-x)); }
__device__ __forceinline__ float ftanh(float x) { return 2.f / (1.f + __expf(-2.f * x)) - 1.f; }

#define MMA(d, A, bb0, bb1) \
    asm volatile("mma.sync.aligned.m16n8k16.row.col.f32.bf16.bf16.f32 " \
                 "{%0,%1,%2,%3},{%4,%5,%6,%7},{%8,%9},{%0,%1,%2,%3};" \
                 : "+f"(d[0]), "+f"(d[1]), "+f"(d[2]), "+f"(d[3]) \
                 : "r"(A[0]), "r"(A[1]), "r"(A[2]), "r"(A[3]), "r"(bb0), "r"(bb1))
#define LDB(bb0, bb1, ad) \
    asm volatile("ldmatrix.sync.aligned.m8n8.x2.trans.shared.b16 {%0,%1}, [%2];" \
                 : "=r"(bb0), "=r"(bb1) : "r"(ad))
#define LDA(A, ad) \
    asm volatile("ldmatrix.sync.aligned.m8n8.x4.shared.b16 {%0,%1,%2,%3}, [%4];" \
                 : "=r"(A[0]), "=r"(A[1]), "=r"(A[2]), "=r"(A[3]) : "r"(ad))

// ---- k_alpha ---------------------------------------------------------------
__global__ void __launch_bounds__(512) k_alpha(const float* __restrict__ inp,
                                               const float* __restrict__ fc_w,
                                               float* __restrict__ ow) {
    __shared__ float wx[128], part[4][128], rm[4], rs[4];
    const int tid = threadIdx.x, b = blockIdx.x, k = tid & 127, tq = tid >> 7;
    if (tid < 128) wx[tid] = (tid < T_) ? fc_w[2 * H_ + tid] : 0.f;
    __syncthreads();
    const float* ib = inp + (size_t)b * T_ * K_;
    float acc = 0.f;
    const int t1 = (tq * 32 + 32 < T_) ? tq * 32 + 32 : T_;
    for (int t = tq * 32; t < t1; t++) acc += ib[t * K_ + k] * wx[t];
    part[tq][k] = acc;
    __syncthreads();
    float a = part[0][k] + part[1][k] + part[2][k] + part[3][k];
    float m = a;
#pragma unroll
    for (int o = 16; o; o >>= 1) m = fmaxf(m, __shfl_xor_sync(~0u, m, o));
    rm[(tid >> 5) & 3] = m; __syncthreads();
    m = fmaxf(fmaxf(rm[0], rm[1]), fmaxf(rm[2], rm[3]));
    float e = __expf(a - m), s = e;
#pragma unroll
    for (int o = 16; o; o >>= 1) s += __shfl_xor_sync(~0u, s, o);
    rs[(tid >> 5) & 3] = s; __syncthreads();
    const float al = e / (rs[0] + rs[1] + rs[2] + rs[3]);
    float* ob = ow + (size_t)b * T_ * K_;
    for (int t = tq; t < T_; t += 4) ob[t * K_ + k] = al * ib[t * K_ + k];
}

// ---- k_xgemm (bf16 mma, ALIGNED): g_gx = xw @ W_ih^T + bias ------------------
// sAhi@0, sAlo@32768 (128bt x 128k bf16, 256B rows)
// sBhi@65536, sBlo@133120 ([128 k][264] bf16, 528B rows = 16B aligned)
// bias@200704 (256 f) ; total 201728 B
#define XGB 201728
__global__ void __launch_bounds__(256, 1) k_xgemm(const float* __restrict__ xw,
                                                  const float* __restrict__ Wih,
                                                  const float* __restrict__ bi,
                                                  const float* __restrict__ bh) {
    extern __shared__ __align__(128) char sx[];
    __nv_bfloat16* sA = (__nv_bfloat16*)sx;
    __nv_bfloat16* sB = (__nv_bfloat16*)(sx + 65536);
    float* bias = (float*)(sx + 200704);
    const int tid = threadIdx.x, w = tid >> 5, lane = tid & 31;
    const int bt0 = (blockIdx.x >> 2) * 128, col0 = (blockIdx.x & 3) * 256;

    for (int i = tid; i < 16384; i += 256) {
        float f = xw[(size_t)(bt0 + (i >> 7)) * K_ + (i & 127)];
        __nv_bfloat16 h = __float2bfloat16(f);
        sA[i] = h;
        sA[16384 + i] = __float2bfloat16(f - __bfloat162float(h));
    }
    for (int i = tid; i < 32768; i += 256) {
        int r = i >> 7, k = i & 127;
        float f = Wih[(size_t)(col0 + r) * K_ + k];
        __nv_bfloat16 h = __float2bfloat16(f);
        sB[k * 264 + r] = h;
        sB[33792 + k * 264 + r] = __float2bfloat16(f - __bfloat162float(h));
    }
    if (tid < 256) bias[tid] = bi[col0 + tid] + bh[col0 + tid];
    __syncthreads();

    unsigned ahi[8][4], alo[8][4];
    const unsigned ao = su32(sx) + (unsigned)((w * 16 + (lane & 15)) * 256 + (lane >> 4) * 16);
#pragma unroll
    for (int kc = 0; kc < 8; kc++) { LDA(ahi[kc], ao + kc * 32); LDA(alo[kc], ao + 32768 + kc * 32); }
    // B: row k stride 528B (16B-aligned); kc advances 16 rows = 8448B; lo plane +67584B
    const unsigned bb = su32(sx) + 65536u + (unsigned)((lane & 15) * 528);

#pragma unroll 1
    for (int nc = 0; nc < 32; nc++) {
        float da[4] = {0,0,0,0}, db[4] = {0,0,0,0}, dc[4] = {0,0,0,0};
#pragma unroll
        for (int kc = 0; kc < 8; kc++) {
            unsigned b0, b1, l0, l1;
            LDB(b0, b1, bb + kc * 8448 + nc * 16);
            LDB(l0, l1, bb + 67584 + kc * 8448 + nc * 16);
            MMA(da, ahi[kc], b0, b1);
            MMA(db, alo[kc], b0, b1);
            MMA(dc, ahi[kc], l0, l1);
        }
        const int c = nc * 8 + (lane & 3) * 2, g = lane >> 2;
        float2 b2 = *(float2*)(bias + c);
        float2 o1 = make_float2(da[0] + db[0] + dc[0] + b2.x, da[1] + db[1] + dc[1] + b2.y);
        float2 o2 = make_float2(da[2] + db[2] + dc[2] + b2.x, da[3] + db[3] + dc[3] + b2.y);
        *(float2*)(g_gx + (size_t)(bt0 + w * 16 + g) * G4_ + col0 + c) = o1;
        *(float2*)(g_gx + (size_t)(bt0 + w * 16 + g + 8) * G4_ + col0 + c) = o2;
    }
}

// ---- k_lstm: EXACT R9/R10 version (passed @1208us) ---------------------------
#define LSMB 110592
__global__ void __launch_bounds__(256, 1) __cluster_dims__(CL_, 1, 1)
k_lstm(const float* __restrict__ W_hh, float* __restrict__ out_h) {
    extern __shared__ __align__(1024) char smc[];
    float* smf = (float*)smc;
    const int tid = threadIdx.x, wid = tid >> 5, lane = tid & 31;
    unsigned rank; asm("mov.u32 %0, %%cluster_ctarank;" : "=r"(rank));
    const int b0 = (blockIdx.x / CL_) * 16;
    const unsigned sb = su32(smc);

    if (tid == 0) {
        mbar_init(sb + 0, 8);  mbar_init(sb + 8, 8);    // full[0], full[1]
        mbar_init(sb + 16, 8); mbar_init(sb + 24, 8);   // empty[0], empty[1]
    }
    for (int i = tid; i < 8192; i += 256) smf[256 + i] = 0.f;   // zero hT

    __nv_bfloat16* Wst = (__nv_bfloat16*)(smc + 45056);
    unsigned ahi[16][4], alo[16][4];
    const unsigned abase = su32(Wst) + (unsigned)((wid * 16 + (lane & 15)) * 512 + (lane >> 4) * 16);
    for (int i = tid; i < 32768; i += 256) {
        int r = i >> 8, k = i & 255;
        int grow = (r >> 5) * H_ + (int)rank * 32 + (r & 31);
        Wst[r * 256 + k] = __float2bfloat16(W_hh[grow * H_ + k]);
    }
    __syncthreads();
#pragma unroll
    for (int kc = 0; kc < 16; kc++) LDA(ahi[kc], abase + kc * 32);
    __syncthreads();
    for (int i = tid; i < 32768; i += 256) {
        int r = i >> 8, k = i & 255;
        int grow = (r >> 5) * H_ + (int)rank * 32 + (r & 31);
        float w = W_hh[grow * H_ + k];
        Wst[r * 256 + k] = __float2bfloat16(w - __bfloat162float(__float2bfloat16(w)));
    }
    __syncthreads();
#pragma unroll
    for (int kc = 0; kc < 16; kc++) LDA(alo[kc], abase + kc * 32);
    __syncthreads();

    unsigned rbase[CL_];
#pragma unroll
    for (int pr = 0; pr < CL_; pr++) rbase[pr] = mapa_rank(sb, pr);

    const unsigned hT0 = sb + 1024;
    const unsigned brow = (unsigned)((lane & 15) * 32);

    const int jl = tid & 31, m0 = tid >> 5;
    float c0 = 0.f, c1 = 0.f;
    float* gt = (float*)(smc + 33792);
    __nv_bfloat16* hs = (__nv_bfloat16*)(smc + 43008);
    float* o0 = out_h + (size_t)(b0 + m0) * T_ * H_ + (int)rank * 32 + jl;
    float* o1 = out_h + (size_t)(b0 + m0 + 8) * T_ * H_ + (int)rank * 32 + jl;
    const float* gxb = g_gx + (size_t)b0 * T_ * G4_ + (int)rank * 32 + jl;

    const int wc = tid & 127;
    const int wjl = wc >> 2, whalf = (wc >> 1) & 1, whl = wc & 1;
    const int rg = (tid >> 7) * 4;
    const uint4* wsrc = (const uint4*)(smc + 43008 + whl * 1024 + wjl * 32 + whalf * 16);
    const unsigned wdst = (unsigned)(1024 + whl * 8192 + ((int)rank * 32 + wjl) * 32 + whalf * 16);

    csync();

    for (int t = 0; t < T_; t++) {
        const int p = t & 1;
        const unsigned pw = (unsigned)(((t - 1) >> 1) & 1);

        const float* gp = gxb + (size_t)t * G4_;
        float gx[8];
#pragma unroll
        for (int q = 0; q < 4; q++) {
            gx[q]     = gp[(size_t)m0 * T_ * G4_ + q * 256];
            gx[4 + q] = gp[(size_t)(m0 + 8) * T_ * G4_ + q * 256];
        }

        float d0[4] = {0.f, 0.f, 0.f, 0.f}, d1[4] = {0.f, 0.f, 0.f, 0.f};
        if (t > 0) {
            if (wid == 0) mwait(sb + p * 8, pw);         // full[p]
            __syncthreads();
            const unsigned bbh = hT0 + (unsigned)p * 16384 + brow;
            float a0[4] = {0,0,0,0}, b0a[4] = {0,0,0,0}, cc0[4] = {0,0,0,0};
            float a1[4] = {0,0,0,0}, b1a[4] = {0,0,0,0}, cc1[4] = {0,0,0,0};
#pragma unroll
            for (int kc = 0; kc < 16; kc++) {
                unsigned bh0, bh1, bl0, bl1, ch0, ch1, cl0, cl1;
                LDB(bh0, bh1, bbh + kc * 512);
                LDB(bl0, bl1, bbh + 8192 + kc * 512);
                LDB(ch0, ch1, bbh + kc * 512 + 16);
                LDB(cl0, cl1, bbh + 8192 + kc * 512 + 16);
                MMA(a0, ahi[kc], bh0, bh1);
                MMA(b0a, alo[kc], bh0, bh1);
                MMA(cc0, ahi[kc], bl0, bl1);
                MMA(a1, ahi[kc], ch0, ch1);
                MMA(b1a, alo[kc], ch0, ch1);
                MMA(cc1, ahi[kc], cl0, cl1);
            }
#pragma unroll
            for (int i = 0; i < 4; i++) {
                d0[i] = a0[i] + b0a[i] + cc0[i];
                d1[i] = a1[i] + b1a[i] + cc1[i];
            }
        }
        {
            int g = lane >> 2, tt = (lane & 3) * 2;
            float* r0 = gt + (wid * 16 + g) * 18;
            float* r1 = r0 + 8 * 18;
            *(float2*)(r0 + tt) = make_float2(d0[0], d0[1]);
            *(float2*)(r1 + tt) = make_float2(d0[2], d0[3]);
            *(float2*)(r0 + 8 + tt) = make_float2(d1[0], d1[1]);
            *(float2*)(r1 + 8 + tt) = make_float2(d1[2], d1[3]);
        }
        __syncthreads();
        if (tid < 8) arr_remote(rbase[tid] + 16 + p * 8);   // release empty[p]

        float gi = gt[jl * 18 + m0] + gx[0];
        float gf = gt[(32 + jl) * 18 + m0] + gx[1];
        float gg = gt[(64 + jl) * 18 + m0] + gx[2];
        float go = gt[(96 + jl) * 18 + m0] + gx[3];
        c0 = sigm(gf) * c0 + sigm(gi) * ftanh(gg);
        float h0 = sigm(go) * ftanh(c0);
        gi = gt[jl * 18 + m0 + 8] + gx[4];
        gf = gt[(32 + jl) * 18 + m0 + 8] + gx[5];
        gg = gt[(64 + jl) * 18 + m0 + 8] + gx[6];
        go = gt[(96 + jl) * 18 + m0 + 8] + gx[7];
        c1 = sigm(gf) * c1 + sigm(gi) * ftanh(gg);
        float h1 = sigm(go) * ftanh(c1);

        o0[(size_t)t * H_] = h0;
        o1[(size_t)t * H_] = h1;

        if (t < T_ - 1) {
            __nv_bfloat16 hh0 = __float2bfloat16(h0), hh1 = __float2bfloat16(h1);
            hs[jl * 16 + m0] = hh0;
            hs[jl * 16 + m0 + 8] = hh1;
            hs[512 + jl * 16 + m0] = __float2bfloat16(h0 - __bfloat162float(hh0));
            hs[512 + jl * 16 + m0 + 8] = __float2bfloat16(h1 - __bfloat162float(hh1));
            if (wid == 0 && t > 0) mwait(sb + 16 + (p ^ 1) * 8, pw);   // empty[p^1]
            __syncthreads();
            uint4 v = *wsrc;
            unsigned drel = wdst + (unsigned)((p ^ 1) * 16384);
#pragma unroll
            for (int i = 0; i < 4; i++) st_cl_v4(rbase[rg + i] + drel, v);
            __syncthreads();
            if (tid < 8) arr_remote(rbase[tid] + (p ^ 1) * 8);   // full[p^1] release
        }
    }
    csync();
}

// ---- launch -----------------------------------------------------------------
extern "C" void kernel_launch(void* const* d_in, const int* in_sizes, int n_in,
                              void* d_out, int out_size) {
    const float* input = (const float*)d_in[0];
    const float* W_ih  = (const float*)d_in[1];
    const float* W_hh  = (const float*)d_in[2];
    const float* b_ih  = (const float*)d_in[3];
    const float* b_hh  = (const float*)d_in[4];
    const float* fc_w  = (const float*)d_in[5];
    float* out   = (float*)d_out;
    float* out_w = out;
    float* out_h = out + (size_t)B_ * T_ * K_;

    cudaFuncSetAttribute(k_xgemm, cudaFuncAttributeMaxDynamicSharedMemorySize, XGB);
    cudaFuncSetAttribute(k_lstm,  cudaFuncAttributeMaxDynamicSharedMemorySize, LSMB);

    k_alpha<<<B_, 512>>>(input, fc_w, out_w);
    k_xgemm<<<(BT_ / 128) * 4, 256, XGB>>>(out_w, W_ih, b_ih, b_hh);
    k_lstm<<<(B_ / 16) * CL_, 256, LSMB>>>(W_hh, out_h);
}